// round 12
// baseline (speedup 1.0000x reference)
#include <cuda_runtime.h>
#include <cstdint>
#include <math.h>

#define HID   2048
#define MROWS 2048      // b*s = 2*1024
#define SEQ   1024
#define NHEADS 32
#define NKV   8
#define HD    64
#define FFND  8192

// ---------------- scratch (static device arrays; no allocation) ----------------
__device__ float d_normed [MROWS * HID];
__device__ float d_q      [MROWS * HID];
__device__ float d_k      [MROWS * NKV * HD];
__device__ float d_v      [MROWS * NKV * HD];
__device__ float d_ctx    [MROWS * HID];
__device__ float d_attn   [MROWS * HID];
__device__ float d_normed2[MROWS * HID];
__device__ float d_g      [MROWS * FFND];
__device__ float d_u      [MROWS * FFND];
__device__ float d_rope   [MROWS * 64];       // per-row cos[32] | sin[32]

// ---------------- helpers ----------------
__device__ __forceinline__ unsigned f2tf(float x) {
    unsigned u;
    asm("cvt.rna.tf32.f32 %0, %1;" : "=r"(u) : "f"(x));
    return u;
}
__device__ __forceinline__ float rndtf(float x) { return __uint_as_float(f2tf(x)); }

// ---------------- RMSNorm (fused optional residual; output tf32-rounded) -------------
__global__ void __launch_bounds__(256) rmsnorm_kernel(
    const float* __restrict__ x, const float* __restrict__ res,
    const float* __restrict__ w, float* __restrict__ out)
{
    int row = blockIdx.x;
    int tid = threadIdx.x;
    const float4* xr = reinterpret_cast<const float4*>(x + (size_t)row * HID);
    float4 v0 = xr[tid];
    float4 v1 = xr[tid + 256];
    if (res) {
        const float4* rr = reinterpret_cast<const float4*>(res + (size_t)row * HID);
        float4 r0 = rr[tid], r1 = rr[tid + 256];
        v0.x += r0.x; v0.y += r0.y; v0.z += r0.z; v0.w += r0.w;
        v1.x += r1.x; v1.y += r1.y; v1.z += r1.z; v1.w += r1.w;
    }
    float ss = v0.x*v0.x + v0.y*v0.y + v0.z*v0.z + v0.w*v0.w
             + v1.x*v1.x + v1.y*v1.y + v1.z*v1.z + v1.w*v1.w;
    #pragma unroll
    for (int o = 16; o; o >>= 1) ss += __shfl_xor_sync(0xffffffffu, ss, o);
    __shared__ float red[8];
    if ((tid & 31) == 0) red[tid >> 5] = ss;
    __syncthreads();
    float tot = red[0] + red[1] + red[2] + red[3] + red[4] + red[5] + red[6] + red[7];
    float sc = rsqrtf(tot / (float)HID + 1e-5f);
    const float4* wr = reinterpret_cast<const float4*>(w);
    float4 w0 = wr[tid], w1 = wr[tid + 256];
    float4 o0 = make_float4(rndtf(v0.x*sc*w0.x), rndtf(v0.y*sc*w0.y),
                            rndtf(v0.z*sc*w0.z), rndtf(v0.w*sc*w0.w));
    float4 o1 = make_float4(rndtf(v1.x*sc*w1.x), rndtf(v1.y*sc*w1.y),
                            rndtf(v1.z*sc*w1.z), rndtf(v1.w*sc*w1.w));
    float4* orow = reinterpret_cast<float4*>(out + (size_t)row * HID);
    orow[tid]       = o0;
    orow[tid + 256] = o1;
}

// ---------------- tf32 GEMM: CTA tile 128x256, warp tile 64x64 (2m x 4n), BK=16 -------
// Crossbar-optimized: frag bytes/mma cut from 1.5 to 1.0 vs the 64x32 warp tile.
// A pre-rounded tf32 (raw frag loads); B converted via f2tf.
// mode: 0 plain, 1 C = acc + Add, 3 C = silu(acc) raw
#define GA_EL 2560                    // As: 128 x 20 (pad 16->20)
#define GB_EL 4224                    // Bs: 16 x 264 (pad 256->264)
#define GSTG  (GA_EL + GB_EL)
#define GEMM_SMEM (2 * GSTG * 4)      // 54272 bytes, 2 stages

__device__ __forceinline__ void gemm_body(
    const float* __restrict__ A, const float* __restrict__ B,
    float* __restrict__ C, const float* __restrict__ Add,
    int N, int K, int bm, int bn, int mode, float* smg)
{
    int tid = threadIdx.x;
    int warp = tid >> 5, lane = tid & 31;
    int wm = (warp >> 2) * 64;        // 0 or 64
    int wn = (warp & 3) * 64;         // 0,64,128,192
    int g = lane >> 2, t = lane & 3;

    int ar0 = tid >> 2, ac0 = (tid & 3) * 4;   // A: 64 rows x 4 chunks (x2 row groups)
    int br0 = tid >> 6, bc0 = (tid & 63) * 4;  // B: 4 rows x 64 chunks (x4 row groups)

    const float* aSrc = A + (size_t)(bm + ar0) * K + ac0;
    const float* bSrc = B + (size_t)br0 * N + bn + bc0;
    const size_t aStep = 64 * (size_t)K;

    float acc[4][8][4] = {};
    int KT = K >> 4;

    auto issue = [&](int buf) {
        float* As = smg + buf * GSTG;
        float* Bs = As + GA_EL;
        unsigned d0 = (unsigned)__cvta_generic_to_shared(&As[ar0 * 20 + ac0]);
        asm volatile("cp.async.cg.shared.global [%0], [%1], 16;\n" :: "r"(d0), "l"(aSrc));
        unsigned d1 = (unsigned)__cvta_generic_to_shared(&As[(ar0 + 64) * 20 + ac0]);
        asm volatile("cp.async.cg.shared.global [%0], [%1], 16;\n" :: "r"(d1), "l"(aSrc + aStep));
        #pragma unroll
        for (int j = 0; j < 4; j++) {
            unsigned d2 = (unsigned)__cvta_generic_to_shared(&Bs[(br0 + 4 * j) * 264 + bc0]);
            asm volatile("cp.async.cg.shared.global [%0], [%1], 16;\n"
                         :: "r"(d2), "l"(bSrc + (size_t)(4 * j) * N));
        }
        asm volatile("cp.async.commit_group;\n");
        aSrc += 16;
        bSrc += (size_t)16 * N;
    };

    issue(0);
    int cur = 0;
    for (int kt = 0; kt < KT; kt++) {
        if (kt + 1 < KT) {
            issue(cur ^ 1);
            asm volatile("cp.async.wait_group 1;\n");
        } else {
            asm volatile("cp.async.wait_group 0;\n");
        }
        __syncthreads();

        const float* As = smg + cur * GSTG;
        const float* Bs = As + GA_EL;

        #pragma unroll
        for (int ks = 0; ks < 16; ks += 8) {
            unsigned a[4][4], b[8][2];
            #pragma unroll
            for (int mi = 0; mi < 4; mi++) {
                int r = wm + mi * 16 + g;
                a[mi][0] = __float_as_uint(As[ r      * 20 + ks + t]);
                a[mi][1] = __float_as_uint(As[(r + 8) * 20 + ks + t]);
                a[mi][2] = __float_as_uint(As[ r      * 20 + ks + t + 4]);
                a[mi][3] = __float_as_uint(As[(r + 8) * 20 + ks + t + 4]);
            }
            #pragma unroll
            for (int ni = 0; ni < 8; ni++) {
                int c = wn + ni * 8 + g;
                b[ni][0] = f2tf(Bs[(ks + t    ) * 264 + c]);
                b[ni][1] = f2tf(Bs[(ks + t + 4) * 264 + c]);
            }
            #pragma unroll
            for (int mi = 0; mi < 4; mi++)
                #pragma unroll
                for (int ni = 0; ni < 8; ni++) {
                    asm volatile(
                        "mma.sync.aligned.m16n8k8.row.col.f32.tf32.tf32.f32 "
                        "{%0,%1,%2,%3},{%4,%5,%6,%7},{%8,%9},{%0,%1,%2,%3};"
                        : "+f"(acc[mi][ni][0]), "+f"(acc[mi][ni][1]),
                          "+f"(acc[mi][ni][2]), "+f"(acc[mi][ni][3])
                        : "r"(a[mi][0]), "r"(a[mi][1]), "r"(a[mi][2]), "r"(a[mi][3]),
                          "r"(b[ni][0]), "r"(b[ni][1]));
                }
        }
        __syncthreads();
        cur ^= 1;
    }

    // epilogue (float2 stores)
    #pragma unroll
    for (int mi = 0; mi < 4; mi++) {
        #pragma unroll
        for (int ni = 0; ni < 8; ni++) {
            int r0 = bm + wm + mi * 16 + g;
            int c0 = bn + wn + ni * 8 + 2 * t;
            size_t i0 = (size_t)r0 * N + c0;
            size_t i1 = i0 + (size_t)8 * N;
            float2 lo = make_float2(acc[mi][ni][0], acc[mi][ni][1]);
            float2 hi = make_float2(acc[mi][ni][2], acc[mi][ni][3]);
            if (mode == 1) {
                const float2 a0 = *reinterpret_cast<const float2*>(Add + i0);
                const float2 a1 = *reinterpret_cast<const float2*>(Add + i1);
                lo.x += a0.x; lo.y += a0.y; hi.x += a1.x; hi.y += a1.y;
            } else if (mode == 3) {
                lo.x = lo.x / (1.f + __expf(-lo.x));
                lo.y = lo.y / (1.f + __expf(-lo.y));
                hi.x = hi.x / (1.f + __expf(-hi.x));
                hi.y = hi.y / (1.f + __expf(-hi.y));
            }
            *reinterpret_cast<float2*>(C + i0) = lo;
            *reinterpret_cast<float2*>(C + i1) = hi;
        }
    }
}

__global__ void __launch_bounds__(256) gemm_tf32(
    const float* __restrict__ A, const float* __restrict__ B,
    float* __restrict__ C, const float* __restrict__ Add,
    int N, int K, int mode)
{
    extern __shared__ float smg[];
    gemm_body(A, B, C, Add, N, K, blockIdx.y * 128, blockIdx.x * 256, mode, smg);
}

// fused QKV (+ rope table build in prologue): grid (12, 16)
// tiles 0-7 -> Q, 8-9 -> K, 10-11 -> V  (256-wide n-tiles)
__global__ void __launch_bounds__(256) qkv_kernel(
    const float* __restrict__ A,
    const float* __restrict__ wq, const float* __restrict__ wk, const float* __restrict__ wv,
    float* __restrict__ q, float* __restrict__ k, float* __restrict__ v,
    const int* __restrict__ posids, float* __restrict__ ropetab)
{
    extern __shared__ float smg[];
    // build rope cos/sin table (65536 entries over 192 blocks x 256 threads)
    {
        int lb = blockIdx.y * 12 + blockIdx.x;
        for (int e = lb * 256 + threadIdx.x; e < MROWS * 32; e += 192 * 256) {
            int row = e >> 5, i = e & 31;
            double invf = exp2(-(double)i * (18.931568569324174 / 32.0)); // 500000^{-i/32}
            float ang = (float)((double)posids[row] * invf);
            float s, c;
            sincosf(ang, &s, &c);
            ropetab[row * 64 + i]      = c;
            ropetab[row * 64 + 32 + i] = s;
        }
    }
    int nt = blockIdx.x, bm = blockIdx.y * 128;
    const float* B; float* Cp; int N, bn;
    if (nt < 8)       { B = wq; Cp = q; N = HID;      bn = nt * 256; }
    else if (nt < 10) { B = wk; Cp = k; N = NKV * HD; bn = (nt - 8) * 256; }
    else              { B = wv; Cp = v; N = NKV * HD; bn = (nt - 10) * 256; }
    gemm_body(A, B, Cp, nullptr, N, HID, bm, bn, 0, smg);
}

// fused up+gate: grid (64, 16); tiles 0-31 -> up (plain), 32-63 -> gate (silu raw)
__global__ void __launch_bounds__(256) upgate_kernel(
    const float* __restrict__ A,
    const float* __restrict__ wup, const float* __restrict__ wgate,
    float* __restrict__ u, float* __restrict__ g)
{
    extern __shared__ float smg[];
    int nt = blockIdx.x, bm = blockIdx.y * 128;
    const float* B; float* Cp; int bn, mode;
    if (nt < 32) { B = wup;   Cp = u; bn = nt * 256;        mode = 0; }
    else         { B = wgate; Cp = g; bn = (nt - 32) * 256; mode = 3; }
    gemm_body(A, B, Cp, nullptr, FFND, HID, bm, bn, mode, smg);
}

// g = tf32_round(silu_g * u)   (g already holds silu(gate))
__global__ void __launch_bounds__(256) swiglu_mul(
    float* __restrict__ g, const float* __restrict__ u, int n4)
{
    int i = blockIdx.x * 256 + threadIdx.x;
    if (i < n4) {
        float4 gv = reinterpret_cast<float4*>(g)[i];
        float4 uv = reinterpret_cast<const float4*>(u)[i];
        gv.x = rndtf(gv.x * uv.x);
        gv.y = rndtf(gv.y * uv.y);
        gv.z = rndtf(gv.z * uv.z);
        gv.w = rndtf(gv.w * uv.w);
        reinterpret_cast<float4*>(g)[i] = gv;
    }
}

// ---------------- RoPE apply (table built inside qkv_kernel) ----------------
__global__ void __launch_bounds__(256) rope_apply(
    float* __restrict__ q, float* __restrict__ k, const float* __restrict__ tab)
{
    int id = blockIdx.x * 256 + threadIdx.x;    // MROWS * 40 * 32
    int row = id / (40 * 32);
    int rem = id - row * (40 * 32);
    int head = rem >> 5;
    int i = rem & 31;
    float c = tab[row * 64 + i], s = tab[row * 64 + 32 + i];
    float* base;
    if (head < NHEADS) base = q + (size_t)row * HID + head * HD;
    else               base = k + (size_t)row * (NKV * HD) + (head - NHEADS) * HD;
    float x1 = base[i], x2 = base[i + 32];
    base[i]      = x1 * c - x2 * s;
    base[i + 32] = x2 * c + x1 * s;
}

// ---------------- tensor-core flash attention (tf32 mma.sync, causal, GQA) -----------
// Operands tf32-rounded at smem store (raw frag loads). Long blocks launch first.
#define APAD 68
#define ATTM_SMEM ((128 + 64 + 128 + 64) * APAD * 4)
__global__ void __launch_bounds__(256) attn_mma(
    const float* __restrict__ q, const float* __restrict__ kk,
    const float* __restrict__ vv, float* __restrict__ ctx)
{
    extern __shared__ float sm[];
    float* Qs = sm;                   // [128][APAD]
    float* Ks = Qs + 128 * APAD;      // [64][APAD]
    float* Ps = Ks + 64 * APAD;       // [128][APAD] (warp-private rows)
    float* Vt = Ps + 128 * APAD;      // [64][APAD]

    int qt = 7 - blockIdx.x;          // long blocks first
    int bh = blockIdx.y;
    int b = bh >> 5, h = bh & 31, kvh = h >> 2;
    const float* qb = q  + ((size_t)b * SEQ + qt * 128) * HID + h * HD;
    const float* kb = kk + (size_t)b * SEQ * (NKV * HD) + kvh * HD;
    const float* vb = vv + (size_t)b * SEQ * (NKV * HD) + kvh * HD;

    int tid = threadIdx.x, warp = tid >> 5, lane = tid & 31;
    int wm = warp * 16;
    int g = lane >> 2, t = lane & 3;

    #pragma unroll
    for (int i = 0; i < 8; i++) {
        int idx = tid + i * 256;
        int r = idx >> 4, c4 = idx & 15;
        float4 val = *reinterpret_cast<const float4*>(qb + (size_t)r * HID + c4 * 4);
        val.x = rndtf(val.x * 0.125f); val.y = rndtf(val.y * 0.125f);
        val.z = rndtf(val.z * 0.125f); val.w = rndtf(val.w * 0.125f);
        *reinterpret_cast<float4*>(Qs + r * APAD + c4 * 4) = val;
    }

    float acc_o[8][4] = {};
    float m_[2] = {-1e30f, -1e30f};
    float l_[2] = {0.f, 0.f};

    int ktmax = 2 * qt + 1;
    for (int kt = 0; kt <= ktmax; kt++) {
        #pragma unroll
        for (int i = 0; i < 4; i++) {
            int idx = tid + i * 256;
            int r = idx >> 4, c4 = idx & 15;
            float4 kval = *reinterpret_cast<const float4*>(kb + (size_t)(kt * 64 + r) * (NKV * HD) + c4 * 4);
            kval.x = rndtf(kval.x); kval.y = rndtf(kval.y);
            kval.z = rndtf(kval.z); kval.w = rndtf(kval.w);
            *reinterpret_cast<float4*>(Ks + r * APAD + c4 * 4) = kval;
            float4 vval = *reinterpret_cast<const float4*>(vb + (size_t)(kt * 64 + r) * (NKV * HD) + c4 * 4);
            Vt[(c4 * 4 + 0) * APAD + r] = rndtf(vval.x);
            Vt[(c4 * 4 + 1) * APAD + r] = rndtf(vval.y);
            Vt[(c4 * 4 + 2) * APAD + r] = rndtf(vval.z);
            Vt[(c4 * 4 + 3) * APAD + r] = rndtf(vval.w);
        }
        __syncthreads();

        float s[8][4] = {};
        #pragma unroll
        for (int k8 = 0; k8 < 64; k8 += 8) {
            unsigned a[4];
            int r = wm + g;
            a[0] = __float_as_uint(Qs[ r      * APAD + k8 + t]);
            a[1] = __float_as_uint(Qs[(r + 8) * APAD + k8 + t]);
            a[2] = __float_as_uint(Qs[ r      * APAD + k8 + t + 4]);
            a[3] = __float_as_uint(Qs[(r + 8) * APAD + k8 + t + 4]);
            #pragma unroll
            for (int ni = 0; ni < 8; ni++) {
                int c = ni * 8 + g;
                unsigned b0 = __float_as_uint(Ks[c * APAD + k8 + t]);
                unsigned b1 = __float_as_uint(Ks[c * APAD + k8 + t + 4]);
                asm volatile(
                    "mma.sync.aligned.m16n8k8.row.col.f32.tf32.tf32.f32 "
                    "{%0,%1,%2,%3},{%4,%5,%6,%7},{%8,%9},{%0,%1,%2,%3};"
                    : "+f"(s[ni][0]), "+f"(s[ni][1]), "+f"(s[ni][2]), "+f"(s[ni][3])
                    : "r"(a[0]), "r"(a[1]), "r"(a[2]), "r"(a[3]), "r"(b0), "r"(b1));
            }
        }

        if (kt >= 2 * qt) {
            int R0 = qt * 128 + wm + g, R1 = R0 + 8;
            #pragma unroll
            for (int ni = 0; ni < 8; ni++) {
                int c0 = kt * 64 + ni * 8 + 2 * t;
                if (c0     > R0) s[ni][0] = -1e30f;
                if (c0 + 1 > R0) s[ni][1] = -1e30f;
                if (c0     > R1) s[ni][2] = -1e30f;
                if (c0 + 1 > R1) s[ni][3] = -1e30f;
            }
        }

        #pragma unroll
        for (int rs = 0; rs < 2; rs++) {
            float mx = -1e30f;
            #pragma unroll
            for (int ni = 0; ni < 8; ni++)
                mx = fmaxf(mx, fmaxf(s[ni][rs*2], s[ni][rs*2+1]));
            mx = fmaxf(mx, __shfl_xor_sync(0xffffffffu, mx, 1));
            mx = fmaxf(mx, __shfl_xor_sync(0xffffffffu, mx, 2));
            float mnew = fmaxf(m_[rs], mx);
            float corr = __expf(m_[rs] - mnew);
            float ps = 0.f;
            #pragma unroll
            for (int ni = 0; ni < 8; ni++) {
                float p0 = __expf(s[ni][rs*2]     - mnew);
                float p1 = __expf(s[ni][rs*2 + 1] - mnew);
                s[ni][rs*2] = p0; s[ni][rs*2+1] = p1;
                ps += p0 + p1;
            }
            ps += __shfl_xor_sync(0xffffffffu, ps, 1);
            ps += __shfl_xor_sync(0xffffffffu, ps, 2);
            l_[rs] = l_[rs] * corr + ps;
            m_[rs] = mnew;
            #pragma unroll
            for (int ni = 0; ni < 8; ni++) {
                acc_o[ni][rs*2]   *= corr;
                acc_o[ni][rs*2+1] *= corr;
            }
        }

        {
            int r0 = wm + g;
            #pragma unroll
            for (int ni = 0; ni < 8; ni++) {
                int c0 = ni * 8 + 2 * t;
                *reinterpret_cast<float2*>(Ps +  r0      * APAD + c0) =
                    make_float2(rndtf(s[ni][0]), rndtf(s[ni][1]));
                *reinterpret_cast<float2*>(Ps + (r0 + 8) * APAD + c0) =
                    make_float2(rndtf(s[ni][2]), rndtf(s[ni][3]));
            }
        }

        #pragma unroll
        for (int k8 = 0; k8 < 64; k8 += 8) {
            unsigned a[4];
            int r = wm + g;
            a[0] = __float_as_uint(Ps[ r      * APAD + k8 + t]);
            a[1] = __float_as_uint(Ps[(r + 8) * APAD + k8 + t]);
            a[2] = __float_as_uint(Ps[ r      * APAD + k8 + t + 4]);
            a[3] = __float_as_uint(Ps[(r + 8) * APAD + k8 + t + 4]);
            #pragma unroll
            for (int ni = 0; ni < 8; ni++) {
                int c = ni * 8 + g;
                unsigned b0 = __float_as_uint(Vt[c * APAD + k8 + t]);
                unsigned b1 = __float_as_uint(Vt[c * APAD + k8 + t + 4]);
                asm volatile(
                    "mma.sync.aligned.m16n8k8.row.col.f32.tf32.tf32.f32 "
                    "{%0,%1,%2,%3},{%4,%5,%6,%7},{%8,%9},{%0,%1,%2,%3};"
                    : "+f"(acc_o[ni][0]), "+f"(acc_o[ni][1]),
                      "+f"(acc_o[ni][2]), "+f"(acc_o[ni][3])
                    : "r"(a[0]), "r"(a[1]), "r"(a[2]), "r"(a[3]), "r"(b0), "r"(b1));
            }
        }
        __syncthreads();
    }

    #pragma unroll
    for (int rs = 0; rs < 2; rs++) {
        float inv = 1.f / l_[rs];
        int r = qt * 128 + wm + rs * 8 + g;
        #pragma unroll
        for (int ni = 0; ni < 8; ni++) {
            int c = ni * 8 + 2 * t;
            float2 o2 = make_float2(rndtf(acc_o[ni][rs*2] * inv),
                                    rndtf(acc_o[ni][rs*2+1] * inv));
            *reinterpret_cast<float2*>(ctx + (size_t)(b * SEQ + r) * HID + h * HD + c) = o2;
        }
    }
}

// ---------------- driver ----------------
extern "C" void kernel_launch(void* const* d_in, const int* in_sizes, int n_in,
                              void* d_out, int out_size)
{
    const float* hidden  = (const float*)d_in[0];
    // d_in[1] = attention_mask (causal; applied analytically)
    const float* wq      = (const float*)d_in[2];
    const float* wk      = (const float*)d_in[3];
    const float* wv      = (const float*)d_in[4];
    const float* wo      = (const float*)d_in[5];
    const float* norm1w  = (const float*)d_in[6];
    const float* norm2w  = (const float*)d_in[7];
    const float* wgate   = (const float*)d_in[8];
    const float* wup     = (const float*)d_in[9];
    const float* wdown   = (const float*)d_in[10];
    const int*   posids  = (const int*)d_in[11];
    float* out = (float*)d_out;

    float *normed, *q, *k, *v, *ctx, *attn, *normed2, *g, *u, *rope;
    cudaGetSymbolAddress((void**)&normed,  d_normed);
    cudaGetSymbolAddress((void**)&q,       d_q);
    cudaGetSymbolAddress((void**)&k,       d_k);
    cudaGetSymbolAddress((void**)&v,       d_v);
    cudaGetSymbolAddress((void**)&ctx,     d_ctx);
    cudaGetSymbolAddress((void**)&attn,    d_attn);
    cudaGetSymbolAddress((void**)&normed2, d_normed2);
    cudaGetSymbolAddress((void**)&g,       d_g);
    cudaGetSymbolAddress((void**)&u,       d_u);
    cudaGetSymbolAddress((void**)&rope,    d_rope);

    cudaFuncSetAttribute(attn_mma,      cudaFuncAttributeMaxDynamicSharedMemorySize, ATTM_SMEM);
    cudaFuncSetAttribute(gemm_tf32,     cudaFuncAttributeMaxDynamicSharedMemorySize, GEMM_SMEM);
    cudaFuncSetAttribute(qkv_kernel,    cudaFuncAttributeMaxDynamicSharedMemorySize, GEMM_SMEM);
    cudaFuncSetAttribute(upgate_kernel, cudaFuncAttributeMaxDynamicSharedMemorySize, GEMM_SMEM);

    // 1) pre-attention norm (tf32-rounded output)
    rmsnorm_kernel<<<MROWS, 256>>>(hidden, nullptr, norm1w, normed);
    // 2) fused QKV projections (+ rope table build)
    qkv_kernel<<<dim3(12, 16), 256, GEMM_SMEM>>>(normed, wq, wk, wv, q, k, v, posids, rope);
    // 3) RoPE apply
    rope_apply<<<(MROWS * 40 * 32) / 256, 256>>>(q, k, rope);
    // 4) attention (launch #4 -> gets profiled by ncu)
    attn_mma<<<dim3(8, 64), 256, ATTM_SMEM>>>(q, k, v, ctx);
    // 5) output projection
    gemm_tf32<<<dim3(8, 16), 256, GEMM_SMEM>>>(ctx, wo, attn, nullptr, HID, HID, 0);
    // 6) post-attention norm (fused residual add, rounded)
    rmsnorm_kernel<<<MROWS, 256>>>(attn, hidden, norm2w, normed2);
    // 7) FFN: up + gate in ONE launch (gate writes raw silu), then multiply+round
    upgate_kernel<<<dim3(64, 16), 256, GEMM_SMEM>>>(normed2, wup, wgate, u, g);
    swiglu_mul<<<(MROWS * FFND / 4 + 255) / 256, 256>>>(g, u, MROWS * FFND / 4);
    // 8) down projection + final residual (attn_out + ff)
    gemm_tf32<<<dim3(8, 16), 256, GEMM_SMEM>>>(g, wdown, out, attn, HID, FFND, 1);
}

// round 13
// speedup vs baseline: 1.0042x; 1.0042x over previous
#include <cuda_runtime.h>
#include <cstdint>
#include <math.h>

#define HID   2048
#define MROWS 2048      // b*s = 2*1024
#define SEQ   1024
#define NHEADS 32
#define NKV   8
#define HD    64
#define FFND  8192

// ---------------- scratch (static device arrays; no allocation) ----------------
__device__ float d_normed [MROWS * HID];
__device__ float d_q      [MROWS * HID];
__device__ float d_k      [MROWS * NKV * HD];
__device__ float d_v      [MROWS * NKV * HD];
__device__ float d_ctx    [MROWS * HID];
__device__ float d_attn   [MROWS * HID];
__device__ float d_normed2[MROWS * HID];
__device__ float d_g      [MROWS * FFND];
__device__ float d_u      [MROWS * FFND];
__device__ float d_rope   [MROWS * 64];       // per-row cos[32] | sin[32]

// ---------------- helpers ----------------
__device__ __forceinline__ unsigned f2tf(float x) {
    unsigned u;
    asm("cvt.rna.tf32.f32 %0, %1;" : "=r"(u) : "f"(x));
    return u;
}
__device__ __forceinline__ float rndtf(float x) { return __uint_as_float(f2tf(x)); }

// ---------------- RMSNorm (fused optional residual; output tf32-rounded) -------------
__global__ void __launch_bounds__(256) rmsnorm_kernel(
    const float* __restrict__ x, const float* __restrict__ res,
    const float* __restrict__ w, float* __restrict__ out)
{
    int row = blockIdx.x;
    int tid = threadIdx.x;
    const float4* xr = reinterpret_cast<const float4*>(x + (size_t)row * HID);
    float4 v0 = xr[tid];
    float4 v1 = xr[tid + 256];
    if (res) {
        const float4* rr = reinterpret_cast<const float4*>(res + (size_t)row * HID);
        float4 r0 = rr[tid], r1 = rr[tid + 256];
        v0.x += r0.x; v0.y += r0.y; v0.z += r0.z; v0.w += r0.w;
        v1.x += r1.x; v1.y += r1.y; v1.z += r1.z; v1.w += r1.w;
    }
    float ss = v0.x*v0.x + v0.y*v0.y + v0.z*v0.z + v0.w*v0.w
             + v1.x*v1.x + v1.y*v1.y + v1.z*v1.z + v1.w*v1.w;
    #pragma unroll
    for (int o = 16; o; o >>= 1) ss += __shfl_xor_sync(0xffffffffu, ss, o);
    __shared__ float red[8];
    if ((tid & 31) == 0) red[tid >> 5] = ss;
    __syncthreads();
    float tot = red[0] + red[1] + red[2] + red[3] + red[4] + red[5] + red[6] + red[7];
    float sc = rsqrtf(tot / (float)HID + 1e-5f);
    const float4* wr = reinterpret_cast<const float4*>(w);
    float4 w0 = wr[tid], w1 = wr[tid + 256];
    float4 o0 = make_float4(rndtf(v0.x*sc*w0.x), rndtf(v0.y*sc*w0.y),
                            rndtf(v0.z*sc*w0.z), rndtf(v0.w*sc*w0.w));
    float4 o1 = make_float4(rndtf(v1.x*sc*w1.x), rndtf(v1.y*sc*w1.y),
                            rndtf(v1.z*sc*w1.z), rndtf(v1.w*sc*w1.w));
    float4* orow = reinterpret_cast<float4*>(out + (size_t)row * HID);
    orow[tid]       = o0;
    orow[tid + 256] = o1;
}

// ---------------- tf32 GEMM: CTA tile 128x256, warp tile 64x64 (2m x 4n), BK=16 -------
// Crossbar-optimized: frag bytes/mma cut from 1.5 to 1.0 vs the 64x32 warp tile.
// A pre-rounded tf32 (raw frag loads); B converted via f2tf.
// mode: 0 plain, 1 C = acc + Add, 3 C = silu(acc) raw
#define GA_EL 2560                    // As: 128 x 20 (pad 16->20)
#define GB_EL 4224                    // Bs: 16 x 264 (pad 256->264)
#define GSTG  (GA_EL + GB_EL)
#define GEMM_SMEM (2 * GSTG * 4)      // 54272 bytes, 2 stages

__device__ __forceinline__ void gemm_body(
    const float* __restrict__ A, const float* __restrict__ B,
    float* __restrict__ C, const float* __restrict__ Add,
    int N, int K, int bm, int bn, int mode, float* smg)
{
    int tid = threadIdx.x;
    int warp = tid >> 5, lane = tid & 31;
    int wm = (warp >> 2) * 64;        // 0 or 64
    int wn = (warp & 3) * 64;         // 0,64,128,192
    int g = lane >> 2, t = lane & 3;

    int ar0 = tid >> 2, ac0 = (tid & 3) * 4;   // A: 64 rows x 4 chunks (x2 row groups)
    int br0 = tid >> 6, bc0 = (tid & 63) * 4;  // B: 4 rows x 64 chunks (x4 row groups)

    const float* aSrc = A + (size_t)(bm + ar0) * K + ac0;
    const float* bSrc = B + (size_t)br0 * N + bn + bc0;
    const size_t aStep = 64 * (size_t)K;

    float acc[4][8][4] = {};
    int KT = K >> 4;

    auto issue = [&](int buf) {
        float* As = smg + buf * GSTG;
        float* Bs = As + GA_EL;
        unsigned d0 = (unsigned)__cvta_generic_to_shared(&As[ar0 * 20 + ac0]);
        asm volatile("cp.async.cg.shared.global [%0], [%1], 16;\n" :: "r"(d0), "l"(aSrc));
        unsigned d1 = (unsigned)__cvta_generic_to_shared(&As[(ar0 + 64) * 20 + ac0]);
        asm volatile("cp.async.cg.shared.global [%0], [%1], 16;\n" :: "r"(d1), "l"(aSrc + aStep));
        #pragma unroll
        for (int j = 0; j < 4; j++) {
            unsigned d2 = (unsigned)__cvta_generic_to_shared(&Bs[(br0 + 4 * j) * 264 + bc0]);
            asm volatile("cp.async.cg.shared.global [%0], [%1], 16;\n"
                         :: "r"(d2), "l"(bSrc + (size_t)(4 * j) * N));
        }
        asm volatile("cp.async.commit_group;\n");
        aSrc += 16;
        bSrc += (size_t)16 * N;
    };

    issue(0);
    int cur = 0;
    for (int kt = 0; kt < KT; kt++) {
        if (kt + 1 < KT) {
            issue(cur ^ 1);
            asm volatile("cp.async.wait_group 1;\n");
        } else {
            asm volatile("cp.async.wait_group 0;\n");
        }
        __syncthreads();

        const float* As = smg + cur * GSTG;
        const float* Bs = As + GA_EL;

        #pragma unroll
        for (int ks = 0; ks < 16; ks += 8) {
            unsigned a[4][4], b[8][2];
            #pragma unroll
            for (int mi = 0; mi < 4; mi++) {
                int r = wm + mi * 16 + g;
                a[mi][0] = __float_as_uint(As[ r      * 20 + ks + t]);
                a[mi][1] = __float_as_uint(As[(r + 8) * 20 + ks + t]);
                a[mi][2] = __float_as_uint(As[ r      * 20 + ks + t + 4]);
                a[mi][3] = __float_as_uint(As[(r + 8) * 20 + ks + t + 4]);
            }
            #pragma unroll
            for (int ni = 0; ni < 8; ni++) {
                int c = wn + ni * 8 + g;
                b[ni][0] = f2tf(Bs[(ks + t    ) * 264 + c]);
                b[ni][1] = f2tf(Bs[(ks + t + 4) * 264 + c]);
            }
            #pragma unroll
            for (int mi = 0; mi < 4; mi++)
                #pragma unroll
                for (int ni = 0; ni < 8; ni++) {
                    asm volatile(
                        "mma.sync.aligned.m16n8k8.row.col.f32.tf32.tf32.f32 "
                        "{%0,%1,%2,%3},{%4,%5,%6,%7},{%8,%9},{%0,%1,%2,%3};"
                        : "+f"(acc[mi][ni][0]), "+f"(acc[mi][ni][1]),
                          "+f"(acc[mi][ni][2]), "+f"(acc[mi][ni][3])
                        : "r"(a[mi][0]), "r"(a[mi][1]), "r"(a[mi][2]), "r"(a[mi][3]),
                          "r"(b[ni][0]), "r"(b[ni][1]));
                }
        }
        __syncthreads();
        cur ^= 1;
    }

    // epilogue (float2 stores)
    #pragma unroll
    for (int mi = 0; mi < 4; mi++) {
        #pragma unroll
        for (int ni = 0; ni < 8; ni++) {
            int r0 = bm + wm + mi * 16 + g;
            int c0 = bn + wn + ni * 8 + 2 * t;
            size_t i0 = (size_t)r0 * N + c0;
            size_t i1 = i0 + (size_t)8 * N;
            float2 lo = make_float2(acc[mi][ni][0], acc[mi][ni][1]);
            float2 hi = make_float2(acc[mi][ni][2], acc[mi][ni][3]);
            if (mode == 1) {
                const float2 a0 = *reinterpret_cast<const float2*>(Add + i0);
                const float2 a1 = *reinterpret_cast<const float2*>(Add + i1);
                lo.x += a0.x; lo.y += a0.y; hi.x += a1.x; hi.y += a1.y;
            } else if (mode == 3) {
                lo.x = lo.x / (1.f + __expf(-lo.x));
                lo.y = lo.y / (1.f + __expf(-lo.y));
                hi.x = hi.x / (1.f + __expf(-hi.x));
                hi.y = hi.y / (1.f + __expf(-hi.y));
            }
            *reinterpret_cast<float2*>(C + i0) = lo;
            *reinterpret_cast<float2*>(C + i1) = hi;
        }
    }
}

__global__ void __launch_bounds__(256) gemm_tf32(
    const float* __restrict__ A, const float* __restrict__ B,
    float* __restrict__ C, const float* __restrict__ Add,
    int N, int K, int mode)
{
    extern __shared__ float smg[];
    gemm_body(A, B, C, Add, N, K, blockIdx.y * 128, blockIdx.x * 256, mode, smg);
}

// fused QKV (+ rope table build in prologue): grid (12, 16)
// tiles 0-7 -> Q, 8-9 -> K, 10-11 -> V  (256-wide n-tiles)
__global__ void __launch_bounds__(256) qkv_kernel(
    const float* __restrict__ A,
    const float* __restrict__ wq, const float* __restrict__ wk, const float* __restrict__ wv,
    float* __restrict__ q, float* __restrict__ k, float* __restrict__ v,
    const int* __restrict__ posids, float* __restrict__ ropetab)
{
    extern __shared__ float smg[];
    // build rope cos/sin table (65536 entries over 192 blocks x 256 threads)
    {
        int lb = blockIdx.y * 12 + blockIdx.x;
        for (int e = lb * 256 + threadIdx.x; e < MROWS * 32; e += 192 * 256) {
            int row = e >> 5, i = e & 31;
            double invf = exp2(-(double)i * (18.931568569324174 / 32.0)); // 500000^{-i/32}
            float ang = (float)((double)posids[row] * invf);
            float s, c;
            sincosf(ang, &s, &c);
            ropetab[row * 64 + i]      = c;
            ropetab[row * 64 + 32 + i] = s;
        }
    }
    int nt = blockIdx.x, bm = blockIdx.y * 128;
    const float* B; float* Cp; int N, bn;
    if (nt < 8)       { B = wq; Cp = q; N = HID;      bn = nt * 256; }
    else if (nt < 10) { B = wk; Cp = k; N = NKV * HD; bn = (nt - 8) * 256; }
    else              { B = wv; Cp = v; N = NKV * HD; bn = (nt - 10) * 256; }
    gemm_body(A, B, Cp, nullptr, N, HID, bm, bn, 0, smg);
}

// fused up+gate: grid (64, 16); tiles 0-31 -> up (plain), 32-63 -> gate (silu raw)
__global__ void __launch_bounds__(256) upgate_kernel(
    const float* __restrict__ A,
    const float* __restrict__ wup, const float* __restrict__ wgate,
    float* __restrict__ u, float* __restrict__ g)
{
    extern __shared__ float smg[];
    int nt = blockIdx.x, bm = blockIdx.y * 128;
    const float* B; float* Cp; int bn, mode;
    if (nt < 32) { B = wup;   Cp = u; bn = nt * 256;        mode = 0; }
    else         { B = wgate; Cp = g; bn = (nt - 32) * 256; mode = 3; }
    gemm_body(A, B, Cp, nullptr, FFND, HID, bm, bn, mode, smg);
}

// g = tf32_round(silu_g * u)   (g already holds silu(gate))
__global__ void __launch_bounds__(256) swiglu_mul(
    float* __restrict__ g, const float* __restrict__ u, int n4)
{
    int i = blockIdx.x * 256 + threadIdx.x;
    if (i < n4) {
        float4 gv = reinterpret_cast<float4*>(g)[i];
        float4 uv = reinterpret_cast<const float4*>(u)[i];
        gv.x = rndtf(gv.x * uv.x);
        gv.y = rndtf(gv.y * uv.y);
        gv.z = rndtf(gv.z * uv.z);
        gv.w = rndtf(gv.w * uv.w);
        reinterpret_cast<float4*>(g)[i] = gv;
    }
}

// ---------------- RoPE apply (table built inside qkv_kernel) ----------------
__global__ void __launch_bounds__(256) rope_apply(
    float* __restrict__ q, float* __restrict__ k, const float* __restrict__ tab)
{
    int id = blockIdx.x * 256 + threadIdx.x;    // MROWS * 40 * 32
    int row = id / (40 * 32);
    int rem = id - row * (40 * 32);
    int head = rem >> 5;
    int i = rem & 31;
    float c = tab[row * 64 + i], s = tab[row * 64 + 32 + i];
    float* base;
    if (head < NHEADS) base = q + (size_t)row * HID + head * HD;
    else               base = k + (size_t)row * (NKV * HD) + (head - NHEADS) * HD;
    float x1 = base[i], x2 = base[i + 32];
    base[i]      = x1 * c - x2 * s;
    base[i + 32] = x2 * c + x1 * s;
}

// ---------------- tensor-core flash attention (tf32 mma.sync, causal, GQA) -----------
// Operands tf32-rounded at smem store (raw frag loads). Long blocks launch first.
#define APAD 68
#define ATTM_SMEM ((128 + 64 + 128 + 64) * APAD * 4)
__global__ void __launch_bounds__(256) attn_mma(
    const float* __restrict__ q, const float* __restrict__ kk,
    const float* __restrict__ vv, float* __restrict__ ctx)
{
    extern __shared__ float sm[];
    float* Qs = sm;                   // [128][APAD]
    float* Ks = Qs + 128 * APAD;      // [64][APAD]
    float* Ps = Ks + 64 * APAD;       // [128][APAD] (warp-private rows)
    float* Vt = Ps + 128 * APAD;      // [64][APAD]

    int qt = 7 - blockIdx.x;          // long blocks first
    int bh = blockIdx.y;
    int b = bh >> 5, h = bh & 31, kvh = h >> 2;
    const float* qb = q  + ((size_t)b * SEQ + qt * 128) * HID + h * HD;
    const float* kb = kk + (size_t)b * SEQ * (NKV * HD) + kvh * HD;
    const float* vb = vv + (size_t)b * SEQ * (NKV * HD) + kvh * HD;

    int tid = threadIdx.x, warp = tid >> 5, lane = tid & 31;
    int wm = warp * 16;
    int g = lane >> 2, t = lane & 3;

    #pragma unroll
    for (int i = 0; i < 8; i++) {
        int idx = tid + i * 256;
        int r = idx >> 4, c4 = idx & 15;
        float4 val = *reinterpret_cast<const float4*>(qb + (size_t)r * HID + c4 * 4);
        val.x = rndtf(val.x * 0.125f); val.y = rndtf(val.y * 0.125f);
        val.z = rndtf(val.z * 0.125f); val.w = rndtf(val.w * 0.125f);
        *reinterpret_cast<float4*>(Qs + r * APAD + c4 * 4) = val;
    }

    float acc_o[8][4] = {};
    float m_[2] = {-1e30f, -1e30f};
    float l_[2] = {0.f, 0.f};

    int ktmax = 2 * qt + 1;
    for (int kt = 0; kt <= ktmax; kt++) {
        #pragma unroll
        for (int i = 0; i < 4; i++) {
            int idx = tid + i * 256;
            int r = idx >> 4, c4 = idx & 15;
            float4 kval = *reinterpret_cast<const float4*>(kb + (size_t)(kt * 64 + r) * (NKV * HD) + c4 * 4);
            kval.x = rndtf(kval.x); kval.y = rndtf(kval.y);
            kval.z = rndtf(kval.z); kval.w = rndtf(kval.w);
            *reinterpret_cast<float4*>(Ks + r * APAD + c4 * 4) = kval;
            float4 vval = *reinterpret_cast<const float4*>(vb + (size_t)(kt * 64 + r) * (NKV * HD) + c4 * 4);
            Vt[(c4 * 4 + 0) * APAD + r] = rndtf(vval.x);
            Vt[(c4 * 4 + 1) * APAD + r] = rndtf(vval.y);
            Vt[(c4 * 4 + 2) * APAD + r] = rndtf(vval.z);
            Vt[(c4 * 4 + 3) * APAD + r] = rndtf(vval.w);
        }
        __syncthreads();

        float s[8][4] = {};
        #pragma unroll
        for (int k8 = 0; k8 < 64; k8 += 8) {
            unsigned a[4];
            int r = wm + g;
            a[0] = __float_as_uint(Qs[ r      * APAD + k8 + t]);
            a[1] = __float_as_uint(Qs[(r + 8) * APAD + k8 + t]);
            a[2] = __float_as_uint(Qs[ r      * APAD + k8 + t + 4]);
            a[3] = __float_as_uint(Qs[(r + 8) * APAD + k8 + t + 4]);
            #pragma unroll
            for (int ni = 0; ni < 8; ni++) {
                int c = ni * 8 + g;
                unsigned b0 = __float_as_uint(Ks[c * APAD + k8 + t]);
                unsigned b1 = __float_as_uint(Ks[c * APAD + k8 + t + 4]);
                asm volatile(
                    "mma.sync.aligned.m16n8k8.row.col.f32.tf32.tf32.f32 "
                    "{%0,%1,%2,%3},{%4,%5,%6,%7},{%8,%9},{%0,%1,%2,%3};"
                    : "+f"(s[ni][0]), "+f"(s[ni][1]), "+f"(s[ni][2]), "+f"(s[ni][3])
                    : "r"(a[0]), "r"(a[1]), "r"(a[2]), "r"(a[3]), "r"(b0), "r"(b1));
            }
        }

        if (kt >= 2 * qt) {
            int R0 = qt * 128 + wm + g, R1 = R0 + 8;
            #pragma unroll
            for (int ni = 0; ni < 8; ni++) {
                int c0 = kt * 64 + ni * 8 + 2 * t;
                if (c0     > R0) s[ni][0] = -1e30f;
                if (c0 + 1 > R0) s[ni][1] = -1e30f;
                if (c0     > R1) s[ni][2] = -1e30f;
                if (c0 + 1 > R1) s[ni][3] = -1e30f;
            }
        }

        #pragma unroll
        for (int rs = 0; rs < 2; rs++) {
            float mx = -1e30f;
            #pragma unroll
            for (int ni = 0; ni < 8; ni++)
                mx = fmaxf(mx, fmaxf(s[ni][rs*2], s[ni][rs*2+1]));
            mx = fmaxf(mx, __shfl_xor_sync(0xffffffffu, mx, 1));
            mx = fmaxf(mx, __shfl_xor_sync(0xffffffffu, mx, 2));
            float mnew = fmaxf(m_[rs], mx);
            float corr = __expf(m_[rs] - mnew);
            float ps = 0.f;
            #pragma unroll
            for (int ni = 0; ni < 8; ni++) {
                float p0 = __expf(s[ni][rs*2]     - mnew);
                float p1 = __expf(s[ni][rs*2 + 1] - mnew);
                s[ni][rs*2] = p0; s[ni][rs*2+1] = p1;
                ps += p0 + p1;
            }
            ps += __shfl_xor_sync(0xffffffffu, ps, 1);
            ps += __shfl_xor_sync(0xffffffffu, ps, 2);
            l_[rs] = l_[rs] * corr + ps;
            m_[rs] = mnew;
            #pragma unroll
            for (int ni = 0; ni < 8; ni++) {
                acc_o[ni][rs*2]   *= corr;
                acc_o[ni][rs*2+1] *= corr;
            }
        }

        {
            int r0 = wm + g;
            #pragma unroll
            for (int ni = 0; ni < 8; ni++) {
                int c0 = ni * 8 + 2 * t;
                *reinterpret_cast<float2*>(Ps +  r0      * APAD + c0) =
                    make_float2(rndtf(s[ni][0]), rndtf(s[ni][1]));
                *reinterpret_cast<float2*>(Ps + (r0 + 8) * APAD + c0) =
                    make_float2(rndtf(s[ni][2]), rndtf(s[ni][3]));
            }
        }

        #pragma unroll
        for (int k8 = 0; k8 < 64; k8 += 8) {
            unsigned a[4];
            int r = wm + g;
            a[0] = __float_as_uint(Ps[ r      * APAD + k8 + t]);
            a[1] = __float_as_uint(Ps[(r + 8) * APAD + k8 + t]);
            a[2] = __float_as_uint(Ps[ r      * APAD + k8 + t + 4]);
            a[3] = __float_as_uint(Ps[(r + 8) * APAD + k8 + t + 4]);
            #pragma unroll
            for (int ni = 0; ni < 8; ni++) {
                int c = ni * 8 + g;
                unsigned b0 = __float_as_uint(Vt[c * APAD + k8 + t]);
                unsigned b1 = __float_as_uint(Vt[c * APAD + k8 + t + 4]);
                asm volatile(
                    "mma.sync.aligned.m16n8k8.row.col.f32.tf32.tf32.f32 "
                    "{%0,%1,%2,%3},{%4,%5,%6,%7},{%8,%9},{%0,%1,%2,%3};"
                    : "+f"(acc_o[ni][0]), "+f"(acc_o[ni][1]),
                      "+f"(acc_o[ni][2]), "+f"(acc_o[ni][3])
                    : "r"(a[0]), "r"(a[1]), "r"(a[2]), "r"(a[3]), "r"(b0), "r"(b1));
            }
        }
        __syncthreads();
    }

    #pragma unroll
    for (int rs = 0; rs < 2; rs++) {
        float inv = 1.f / l_[rs];
        int r = qt * 128 + wm + rs * 8 + g;
        #pragma unroll
        for (int ni = 0; ni < 8; ni++) {
            int c = ni * 8 + 2 * t;
            float2 o2 = make_float2(rndtf(acc_o[ni][rs*2] * inv),
                                    rndtf(acc_o[ni][rs*2+1] * inv));
            *reinterpret_cast<float2*>(ctx + (size_t)(b * SEQ + r) * HID + h * HD + c) = o2;
        }
    }
}

// ---------------- driver ----------------
extern "C" void kernel_launch(void* const* d_in, const int* in_sizes, int n_in,
                              void* d_out, int out_size)
{
    const float* hidden  = (const float*)d_in[0];
    // d_in[1] = attention_mask (causal; applied analytically)
    const float* wq      = (const float*)d_in[2];
    const float* wk      = (const float*)d_in[3];
    const float* wv      = (const float*)d_in[4];
    const float* wo      = (const float*)d_in[5];
    const float* norm1w  = (const float*)d_in[6];
    const float* norm2w  = (const float*)d_in[7];
    const float* wgate   = (const float*)d_in[8];
    const float* wup     = (const float*)d_in[9];
    const float* wdown   = (const float*)d_in[10];
    const int*   posids  = (const int*)d_in[11];
    float* out = (float*)d_out;

    float *normed, *q, *k, *v, *ctx, *attn, *normed2, *g, *u, *rope;
    cudaGetSymbolAddress((void**)&normed,  d_normed);
    cudaGetSymbolAddress((void**)&q,       d_q);
    cudaGetSymbolAddress((void**)&k,       d_k);
    cudaGetSymbolAddress((void**)&v,       d_v);
    cudaGetSymbolAddress((void**)&ctx,     d_ctx);
    cudaGetSymbolAddress((void**)&attn,    d_attn);
    cudaGetSymbolAddress((void**)&normed2, d_normed2);
    cudaGetSymbolAddress((void**)&g,       d_g);
    cudaGetSymbolAddress((void**)&u,       d_u);
    cudaGetSymbolAddress((void**)&rope,    d_rope);

    cudaFuncSetAttribute(attn_mma,      cudaFuncAttributeMaxDynamicSharedMemorySize, ATTM_SMEM);
    cudaFuncSetAttribute(gemm_tf32,     cudaFuncAttributeMaxDynamicSharedMemorySize, GEMM_SMEM);
    cudaFuncSetAttribute(qkv_kernel,    cudaFuncAttributeMaxDynamicSharedMemorySize, GEMM_SMEM);
    cudaFuncSetAttribute(upgate_kernel, cudaFuncAttributeMaxDynamicSharedMemorySize, GEMM_SMEM);

    // 1) pre-attention norm (tf32-rounded output)
    rmsnorm_kernel<<<MROWS, 256>>>(hidden, nullptr, norm1w, normed);
    // 2) fused QKV projections (+ rope table build)
    qkv_kernel<<<dim3(12, 16), 256, GEMM_SMEM>>>(normed, wq, wk, wv, q, k, v, posids, rope);
    // 3) RoPE apply
    rope_apply<<<(MROWS * 40 * 32) / 256, 256>>>(q, k, rope);
    // 4) attention (launch #4 -> gets profiled by ncu)
    attn_mma<<<dim3(8, 64), 256, ATTM_SMEM>>>(q, k, v, ctx);
    // 5) output projection
    gemm_tf32<<<dim3(8, 16), 256, GEMM_SMEM>>>(ctx, wo, attn, nullptr, HID, HID, 0);
    // 6) post-attention norm (fused residual add, rounded)
    rmsnorm_kernel<<<MROWS, 256>>>(attn, hidden, norm2w, normed2);
    // 7) FFN: up + gate in ONE launch (gate writes raw silu), then multiply+round
    upgate_kernel<<<dim3(64, 16), 256, GEMM_SMEM>>>(normed2, wup, wgate, u, g);
    swiglu_mul<<<(MROWS * FFND / 4 + 255) / 256, 256>>>(g, u, MROWS * FFND / 4);
    // 8) down projection + final residual (attn_out + ff)
    gemm_tf32<<<dim3(8, 16), 256, GEMM_SMEM>>>(g, wdown, out, attn, HID, FFND, 1);
}

// round 14
// speedup vs baseline: 1.4381x; 1.4321x over previous
#include <cuda_runtime.h>
#include <cuda_fp16.h>
#include <cstdint>
#include <math.h>

#define HID   2048
#define MROWS 2048      // b*s = 2*1024
#define SEQ   1024
#define NHEADS 32
#define NKV   8
#define HD    64
#define FFND  8192

// ---------------- scratch (static device arrays; no allocation) ----------------
__device__ float  d_q      [MROWS * HID];
__device__ float  d_k      [MROWS * NKV * HD];
__device__ float  d_v      [MROWS * NKV * HD];
__device__ float  d_attn   [MROWS * HID];
__device__ float  d_g      [MROWS * FFND];
__device__ float  d_u      [MROWS * FFND];
__device__ float  d_rope   [MROWS * 64];      // per-row cos[32] | sin[32]
__device__ __half d_normed_h [MROWS * HID];
__device__ __half d_ctx_h    [MROWS * HID];
__device__ __half d_normed2_h[MROWS * HID];
__device__ __half d_g_h      [MROWS * FFND];
// transposed fp16 weights [N, K] (rebuilt every replay; pure function of inputs)
__device__ __half d_wq_t[2048 * 2048];
__device__ __half d_wk_t[512 * 2048];
__device__ __half d_wv_t[512 * 2048];
__device__ __half d_wo_t[2048 * 2048];
__device__ __half d_wg_t[8192 * 2048];
__device__ __half d_wu_t[8192 * 2048];
__device__ __half d_wd_t[2048 * 8192];

// ---------------- weight transpose + fp16 convert: out[c*R + r] = h(in[r*C + c]) -----
__global__ void __launch_bounds__(256) transpose_half(
    const float* __restrict__ in, __half* __restrict__ out, int R, int C)
{
    __shared__ float tile[32][33];
    int bx = blockIdx.x * 32, by = blockIdx.y * 32;
    int tx = threadIdx.x & 31, ty = threadIdx.x >> 5;   // 32 x 8
    #pragma unroll
    for (int i = 0; i < 32; i += 8)
        tile[ty + i][tx] = in[(size_t)(by + ty + i) * C + bx + tx];
    __syncthreads();
    #pragma unroll
    for (int i = 0; i < 32; i += 8)
        out[(size_t)(bx + ty + i) * R + by + tx] = __float2half_rn(tile[tx][ty + i]);
}

// ---------------- RMSNorm (fused optional residual; fp16 output -> GEMM A operand) ---
__global__ void __launch_bounds__(256) rmsnorm_kernel(
    const float* __restrict__ x, const float* __restrict__ res,
    const float* __restrict__ w, __half* __restrict__ out)
{
    int row = blockIdx.x;
    int tid = threadIdx.x;
    const float4* xr = reinterpret_cast<const float4*>(x + (size_t)row * HID);
    float4 v0 = xr[tid];
    float4 v1 = xr[tid + 256];
    if (res) {
        const float4* rr = reinterpret_cast<const float4*>(res + (size_t)row * HID);
        float4 r0 = rr[tid], r1 = rr[tid + 256];
        v0.x += r0.x; v0.y += r0.y; v0.z += r0.z; v0.w += r0.w;
        v1.x += r1.x; v1.y += r1.y; v1.z += r1.z; v1.w += r1.w;
    }
    float ss = v0.x*v0.x + v0.y*v0.y + v0.z*v0.z + v0.w*v0.w
             + v1.x*v1.x + v1.y*v1.y + v1.z*v1.z + v1.w*v1.w;
    #pragma unroll
    for (int o = 16; o; o >>= 1) ss += __shfl_xor_sync(0xffffffffu, ss, o);
    __shared__ float red[8];
    if ((tid & 31) == 0) red[tid >> 5] = ss;
    __syncthreads();
    float tot = red[0] + red[1] + red[2] + red[3] + red[4] + red[5] + red[6] + red[7];
    float sc = rsqrtf(tot / (float)HID + 1e-5f);
    const float4* wr = reinterpret_cast<const float4*>(w);
    float4 w0 = wr[tid], w1 = wr[tid + 256];
    __half2* orow = reinterpret_cast<__half2*>(out + (size_t)row * HID);
    orow[tid * 2]           = __floats2half2_rn(v0.x*sc*w0.x, v0.y*sc*w0.y);
    orow[tid * 2 + 1]       = __floats2half2_rn(v0.z*sc*w0.z, v0.w*sc*w0.w);
    orow[(tid + 256) * 2]   = __floats2half2_rn(v1.x*sc*w1.x, v1.y*sc*w1.y);
    orow[(tid + 256) * 2+1] = __floats2half2_rn(v1.z*sc*w1.z, v1.w*sc*w1.w);
}

// ---------------- fp16 GEMM: CTA 128x128, warp 64x32 (2m x 4n), BK=32, 2-stage -------
// A: half [M,K] row-major. Bt: half [N,K] row-major (pre-transposed weights).
// Both fragment operands are contiguous half2 loads. C: fp32.
// mode: 0 plain, 1 C = acc + Add, 3 C = silu(acc) raw
__device__ __forceinline__ void gemm_body(
    const __half* __restrict__ A, const __half* __restrict__ Bt,
    float* __restrict__ C, const float* __restrict__ Add,
    int N, int K, int bm, int bn, int mode)
{
    __shared__ __half As[2][128][40];   // 32 data + 8 pad: stride 20 banks -> conflict-free
    __shared__ __half Bs[2][128][40];

    int tid = threadIdx.x;
    int warp = tid >> 5, lane = tid & 31;
    int wm = (warp >> 2) * 64, wn = (warp & 3) * 32;
    int g = lane >> 2, t = lane & 3;

    int lrow = tid >> 1;                 // 0..127
    int lcb  = (tid & 1) * 16;           // half-chunk base: 0 or 16

    const __half* aSrc = A  + (size_t)(bm + lrow) * K + lcb;
    const __half* bSrc = Bt + (size_t)(bn + lrow) * K + lcb;

    float acc[4][4][4] = {};
    int KT = K >> 5;

    auto issue = [&](int buf) {
        unsigned d0 = (unsigned)__cvta_generic_to_shared(&As[buf][lrow][lcb]);
        asm volatile("cp.async.cg.shared.global [%0], [%1], 16;\n" :: "r"(d0), "l"(aSrc));
        asm volatile("cp.async.cg.shared.global [%0], [%1], 16;\n" :: "r"(d0 + 16), "l"(aSrc + 8));
        unsigned d1 = (unsigned)__cvta_generic_to_shared(&Bs[buf][lrow][lcb]);
        asm volatile("cp.async.cg.shared.global [%0], [%1], 16;\n" :: "r"(d1), "l"(bSrc));
        asm volatile("cp.async.cg.shared.global [%0], [%1], 16;\n" :: "r"(d1 + 16), "l"(bSrc + 8));
        asm volatile("cp.async.commit_group;\n");
        aSrc += 32;
        bSrc += 32;
    };

    issue(0);
    int cur = 0;
    for (int kt = 0; kt < KT; kt++) {
        if (kt + 1 < KT) {
            issue(cur ^ 1);
            asm volatile("cp.async.wait_group 1;\n");
        } else {
            asm volatile("cp.async.wait_group 0;\n");
        }
        __syncthreads();

        #pragma unroll
        for (int ks = 0; ks < 32; ks += 16) {
            uint32_t a[4][4], b[4][2];
            #pragma unroll
            for (int mi = 0; mi < 4; mi++) {
                int r = wm + mi * 16 + g;
                a[mi][0] = *reinterpret_cast<const uint32_t*>(&As[cur][r    ][ks + 2*t]);
                a[mi][1] = *reinterpret_cast<const uint32_t*>(&As[cur][r + 8][ks + 2*t]);
                a[mi][2] = *reinterpret_cast<const uint32_t*>(&As[cur][r    ][ks + 2*t + 8]);
                a[mi][3] = *reinterpret_cast<const uint32_t*>(&As[cur][r + 8][ks + 2*t + 8]);
            }
            #pragma unroll
            for (int ni = 0; ni < 4; ni++) {
                int c = wn + ni * 8 + g;
                b[ni][0] = *reinterpret_cast<const uint32_t*>(&Bs[cur][c][ks + 2*t]);
                b[ni][1] = *reinterpret_cast<const uint32_t*>(&Bs[cur][c][ks + 2*t + 8]);
            }
            #pragma unroll
            for (int mi = 0; mi < 4; mi++)
                #pragma unroll
                for (int ni = 0; ni < 4; ni++) {
                    asm volatile(
                        "mma.sync.aligned.m16n8k16.row.col.f32.f16.f16.f32 "
                        "{%0,%1,%2,%3},{%4,%5,%6,%7},{%8,%9},{%0,%1,%2,%3};"
                        : "+f"(acc[mi][ni][0]), "+f"(acc[mi][ni][1]),
                          "+f"(acc[mi][ni][2]), "+f"(acc[mi][ni][3])
                        : "r"(a[mi][0]), "r"(a[mi][1]), "r"(a[mi][2]), "r"(a[mi][3]),
                          "r"(b[ni][0]), "r"(b[ni][1]));
                }
        }
        __syncthreads();
        cur ^= 1;
    }

    // epilogue (float2 stores)
    #pragma unroll
    for (int mi = 0; mi < 4; mi++) {
        #pragma unroll
        for (int ni = 0; ni < 4; ni++) {
            int r0 = bm + wm + mi * 16 + g;
            int c0 = bn + wn + ni * 8 + 2 * t;
            size_t i0 = (size_t)r0 * N + c0;
            size_t i1 = i0 + (size_t)8 * N;
            float2 lo = make_float2(acc[mi][ni][0], acc[mi][ni][1]);
            float2 hi = make_float2(acc[mi][ni][2], acc[mi][ni][3]);
            if (mode == 1) {
                const float2 a0 = *reinterpret_cast<const float2*>(Add + i0);
                const float2 a1 = *reinterpret_cast<const float2*>(Add + i1);
                lo.x += a0.x; lo.y += a0.y; hi.x += a1.x; hi.y += a1.y;
            } else if (mode == 3) {
                lo.x = lo.x / (1.f + __expf(-lo.x));
                lo.y = lo.y / (1.f + __expf(-lo.y));
                hi.x = hi.x / (1.f + __expf(-hi.x));
                hi.y = hi.y / (1.f + __expf(-hi.y));
            }
            *reinterpret_cast<float2*>(C + i0) = lo;
            *reinterpret_cast<float2*>(C + i1) = hi;
        }
    }
}

__global__ void __launch_bounds__(256) gemm_h(
    const __half* __restrict__ A, const __half* __restrict__ Bt,
    float* __restrict__ C, const float* __restrict__ Add,
    int N, int K, int mode)
{
    gemm_body(A, Bt, C, Add, N, K, blockIdx.y * 128, blockIdx.x * 128, mode);
}

// fused QKV (+ rope table build): grid (24,16); tiles 0-15 Q, 16-19 K, 20-23 V
__global__ void __launch_bounds__(256) qkv_kernel(
    const __half* __restrict__ A,
    const __half* __restrict__ wq_t, const __half* __restrict__ wk_t, const __half* __restrict__ wv_t,
    float* __restrict__ q, float* __restrict__ k, float* __restrict__ v,
    const int* __restrict__ posids, float* __restrict__ ropetab)
{
    {
        int lb = blockIdx.y * 24 + blockIdx.x;
        for (int e = lb * 256 + threadIdx.x; e < MROWS * 32; e += 384 * 256) {
            int row = e >> 5, i = e & 31;
            double invf = exp2(-(double)i * (18.931568569324174 / 32.0)); // 500000^{-i/32}
            float ang = (float)((double)posids[row] * invf);
            float s, c;
            sincosf(ang, &s, &c);
            ropetab[row * 64 + i]      = c;
            ropetab[row * 64 + 32 + i] = s;
        }
    }
    int nt = blockIdx.x, bm = blockIdx.y * 128;
    const __half* Bt; float* Cp; int N, bn;
    if (nt < 16)      { Bt = wq_t; Cp = q; N = HID;      bn = nt * 128; }
    else if (nt < 20) { Bt = wk_t; Cp = k; N = NKV * HD; bn = (nt - 16) * 128; }
    else              { Bt = wv_t; Cp = v; N = NKV * HD; bn = (nt - 20) * 128; }
    gemm_body(A, Bt, Cp, nullptr, N, HID, bm, bn, 0);
}

// fused up+gate: grid (128,16); tiles 0-63 up (plain), 64-127 gate (silu raw)
__global__ void __launch_bounds__(256) upgate_kernel(
    const __half* __restrict__ A,
    const __half* __restrict__ wu_t, const __half* __restrict__ wg_t,
    float* __restrict__ u, float* __restrict__ g)
{
    int nt = blockIdx.x, bm = blockIdx.y * 128;
    const __half* Bt; float* Cp; int bn, mode;
    if (nt < 64) { Bt = wu_t; Cp = u; bn = nt * 128;        mode = 0; }
    else         { Bt = wg_t; Cp = g; bn = (nt - 64) * 128; mode = 3; }
    gemm_body(A, Bt, Cp, nullptr, FFND, HID, bm, bn, mode);
}

// g_h = half(silu_g * u)
__global__ void __launch_bounds__(256) swiglu_mul(
    const float* __restrict__ g, const float* __restrict__ u, __half* __restrict__ gh, int n4)
{
    int i = blockIdx.x * 256 + threadIdx.x;
    if (i < n4) {
        float4 gv = reinterpret_cast<const float4*>(g)[i];
        float4 uv = reinterpret_cast<const float4*>(u)[i];
        __half2* o = reinterpret_cast<__half2*>(gh) + i * 2;
        o[0] = __floats2half2_rn(gv.x * uv.x, gv.y * uv.y);
        o[1] = __floats2half2_rn(gv.z * uv.z, gv.w * uv.w);
    }
}

// ---------------- RoPE apply ----------------
__global__ void __launch_bounds__(256) rope_apply(
    float* __restrict__ q, float* __restrict__ k, const float* __restrict__ tab)
{
    int id = blockIdx.x * 256 + threadIdx.x;    // MROWS * 40 * 32
    int row = id / (40 * 32);
    int rem = id - row * (40 * 32);
    int head = rem >> 5;
    int i = rem & 31;
    float c = tab[row * 64 + i], s = tab[row * 64 + 32 + i];
    float* base;
    if (head < NHEADS) base = q + (size_t)row * HID + head * HD;
    else               base = k + (size_t)row * (NKV * HD) + (head - NHEADS) * HD;
    float x1 = base[i], x2 = base[i + 32];
    base[i]      = x1 * c - x2 * s;
    base[i + 32] = x2 * c + x1 * s;
}

// ---------------- fp16 tensor-core flash attention (causal, GQA) ---------------------
// smem operands fp16 (pad 64->72 halves: stride 36 banks ≡ 4 -> conflict-free);
// softmax + O accumulators fp32. Warp owns 16 q-rows x all 64 keys. Long blocks first.
#define APADH 72
#define ATTM_SMEM ((128 + 64 + 128 + 64) * APADH * 2)
__global__ void __launch_bounds__(256) attn_mma(
    const float* __restrict__ q, const float* __restrict__ kk,
    const float* __restrict__ vv, __half* __restrict__ ctx)
{
    extern __shared__ __half smh[];
    __half* Qs = smh;                    // [128][APADH]
    __half* Ks = Qs + 128 * APADH;       // [64][APADH]
    __half* Ps = Ks + 64 * APADH;        // [128][APADH] (warp-private rows)
    __half* Vt = Ps + 128 * APADH;       // [64][APADH]  dim-major, key contiguous

    int qt = 7 - blockIdx.x;
    int bh = blockIdx.y;
    int b = bh >> 5, h = bh & 31, kvh = h >> 2;
    const float* qb = q  + ((size_t)b * SEQ + qt * 128) * HID + h * HD;
    const float* kb = kk + (size_t)b * SEQ * (NKV * HD) + kvh * HD;
    const float* vb = vv + (size_t)b * SEQ * (NKV * HD) + kvh * HD;

    int tid = threadIdx.x, warp = tid >> 5, lane = tid & 31;
    int wm = warp * 16;
    int g = lane >> 2, t = lane & 3;

    // load Q (128x64), scale 1/8, convert fp16
    #pragma unroll
    for (int i = 0; i < 8; i++) {
        int idx = tid + i * 256;
        int r = idx >> 4, c4 = idx & 15;
        float4 val = *reinterpret_cast<const float4*>(qb + (size_t)r * HID + c4 * 4);
        __half2* dst = reinterpret_cast<__half2*>(&Qs[r * APADH + c4 * 4]);
        dst[0] = __floats2half2_rn(val.x * 0.125f, val.y * 0.125f);
        dst[1] = __floats2half2_rn(val.z * 0.125f, val.w * 0.125f);
    }

    float acc_o[8][4] = {};
    float m_[2] = {-1e30f, -1e30f};
    float l_[2] = {0.f, 0.f};

    int ktmax = 2 * qt + 1;
    for (int kt = 0; kt <= ktmax; kt++) {
        #pragma unroll
        for (int i = 0; i < 4; i++) {
            int idx = tid + i * 256;
            int r = idx >> 4, c4 = idx & 15;
            float4 kval = *reinterpret_cast<const float4*>(kb + (size_t)(kt * 64 + r) * (NKV * HD) + c4 * 4);
            __half2* kdst = reinterpret_cast<__half2*>(&Ks[r * APADH + c4 * 4]);
            kdst[0] = __floats2half2_rn(kval.x, kval.y);
            kdst[1] = __floats2half2_rn(kval.z, kval.w);
            float4 vval = *reinterpret_cast<const float4*>(vb + (size_t)(kt * 64 + r) * (NKV * HD) + c4 * 4);
            Vt[(c4 * 4 + 0) * APADH + r] = __float2half_rn(vval.x);
            Vt[(c4 * 4 + 1) * APADH + r] = __float2half_rn(vval.y);
            Vt[(c4 * 4 + 2) * APADH + r] = __float2half_rn(vval.z);
            Vt[(c4 * 4 + 3) * APADH + r] = __float2half_rn(vval.w);
        }
        __syncthreads();

        // S = Qs @ Ks^T   (m16n8k16, 4 k-steps)
        float s[8][4] = {};
        #pragma unroll
        for (int ks = 0; ks < 64; ks += 16) {
            uint32_t a[4];
            int r = wm + g;
            a[0] = *reinterpret_cast<const uint32_t*>(&Qs[ r      * APADH + ks + 2*t]);
            a[1] = *reinterpret_cast<const uint32_t*>(&Qs[(r + 8) * APADH + ks + 2*t]);
            a[2] = *reinterpret_cast<const uint32_t*>(&Qs[ r      * APADH + ks + 2*t + 8]);
            a[3] = *reinterpret_cast<const uint32_t*>(&Qs[(r + 8) * APADH + ks + 2*t + 8]);
            #pragma unroll
            for (int ni = 0; ni < 8; ni++) {
                int c = ni * 8 + g;
                uint32_t b0 = *reinterpret_cast<const uint32_t*>(&Ks[c * APADH + ks + 2*t]);
                uint32_t b1 = *reinterpret_cast<const uint32_t*>(&Ks[c * APADH + ks + 2*t + 8]);
                asm volatile(
                    "mma.sync.aligned.m16n8k16.row.col.f32.f16.f16.f32 "
                    "{%0,%1,%2,%3},{%4,%5,%6,%7},{%8,%9},{%0,%1,%2,%3};"
                    : "+f"(s[ni][0]), "+f"(s[ni][1]), "+f"(s[ni][2]), "+f"(s[ni][3])
                    : "r"(a[0]), "r"(a[1]), "r"(a[2]), "r"(a[3]), "r"(b0), "r"(b1));
            }
        }

        if (kt >= 2 * qt) {
            int R0 = qt * 128 + wm + g, R1 = R0 + 8;
            #pragma unroll
            for (int ni = 0; ni < 8; ni++) {
                int c0 = kt * 64 + ni * 8 + 2 * t;
                if (c0     > R0) s[ni][0] = -1e30f;
                if (c0 + 1 > R0) s[ni][1] = -1e30f;
                if (c0     > R1) s[ni][2] = -1e30f;
                if (c0 + 1 > R1) s[ni][3] = -1e30f;
            }
        }

        #pragma unroll
        for (int rs = 0; rs < 2; rs++) {
            float mx = -1e30f;
            #pragma unroll
            for (int ni = 0; ni < 8; ni++)
                mx = fmaxf(mx, fmaxf(s[ni][rs*2], s[ni][rs*2+1]));
            mx = fmaxf(mx, __shfl_xor_sync(0xffffffffu, mx, 1));
            mx = fmaxf(mx, __shfl_xor_sync(0xffffffffu, mx, 2));
            float mnew = fmaxf(m_[rs], mx);
            float corr = __expf(m_[rs] - mnew);
            float ps = 0.f;
            #pragma unroll
            for (int ni = 0; ni < 8; ni++) {
                float p0 = __expf(s[ni][rs*2]     - mnew);
                float p1 = __expf(s[ni][rs*2 + 1] - mnew);
                s[ni][rs*2] = p0; s[ni][rs*2+1] = p1;
                ps += p0 + p1;
            }
            ps += __shfl_xor_sync(0xffffffffu, ps, 1);
            ps += __shfl_xor_sync(0xffffffffu, ps, 2);
            l_[rs] = l_[rs] * corr + ps;
            m_[rs] = mnew;
            #pragma unroll
            for (int ni = 0; ni < 8; ni++) {
                acc_o[ni][rs*2]   *= corr;
                acc_o[ni][rs*2+1] *= corr;
            }
        }

        // write P (fp16) to warp-private rows
        {
            int r0 = wm + g;
            #pragma unroll
            for (int ni = 0; ni < 8; ni++) {
                int c0 = ni * 8 + 2 * t;
                *reinterpret_cast<__half2*>(&Ps[ r0      * APADH + c0]) =
                    __floats2half2_rn(s[ni][0], s[ni][1]);
                *reinterpret_cast<__half2*>(&Ps[(r0 + 8) * APADH + c0]) =
                    __floats2half2_rn(s[ni][2], s[ni][3]);
            }
        }

        // O += P @ V
        #pragma unroll
        for (int ks = 0; ks < 64; ks += 16) {
            uint32_t a[4];
            int r = wm + g;
            a[0] = *reinterpret_cast<const uint32_t*>(&Ps[ r      * APADH + ks + 2*t]);
            a[1] = *reinterpret_cast<const uint32_t*>(&Ps[(r + 8) * APADH + ks + 2*t]);
            a[2] = *reinterpret_cast<const uint32_t*>(&Ps[ r      * APADH + ks + 2*t + 8]);
            a[3] = *reinterpret_cast<const uint32_t*>(&Ps[(r + 8) * APADH + ks + 2*t + 8]);
            #pragma unroll
            for (int ni = 0; ni < 8; ni++) {
                int c = ni * 8 + g;
                uint32_t b0 = *reinterpret_cast<const uint32_t*>(&Vt[c * APADH + ks + 2*t]);
                uint32_t b1 = *reinterpret_cast<const uint32_t*>(&Vt[c * APADH + ks + 2*t + 8]);
                asm volatile(
                    "mma.sync.aligned.m16n8k16.row.col.f32.f16.f16.f32 "
                    "{%0,%1,%2,%3},{%4,%5,%6,%7},{%8,%9},{%0,%1,%2,%3};"
                    : "+f"(acc_o[ni][0]), "+f"(acc_o[ni][1]),
                      "+f"(acc_o[ni][2]), "+f"(acc_o[ni][3])
                    : "r"(a[0]), "r"(a[1]), "r"(a[2]), "r"(a[3]), "r"(b0), "r"(b1));
            }
        }
        __syncthreads();
    }

    // epilogue: divide by l, fp16 ctx (feeds WO GEMM)
    #pragma unroll
    for (int rs = 0; rs < 2; rs++) {
        float inv = 1.f / l_[rs];
        int r = qt * 128 + wm + rs * 8 + g;
        #pragma unroll
        for (int ni = 0; ni < 8; ni++) {
            int c = ni * 8 + 2 * t;
            *reinterpret_cast<__half2*>(ctx + (size_t)(b * SEQ + r) * HID + h * HD + c) =
                __floats2half2_rn(acc_o[ni][rs*2] * inv, acc_o[ni][rs*2+1] * inv);
        }
    }
}

// ---------------- driver ----------------
extern "C" void kernel_launch(void* const* d_in, const int* in_sizes, int n_in,
                              void* d_out, int out_size)
{
    const float* hidden  = (const float*)d_in[0];
    // d_in[1] = attention_mask (causal; applied analytically)
    const float* wq      = (const float*)d_in[2];
    const float* wk      = (const float*)d_in[3];
    const float* wv      = (const float*)d_in[4];
    const float* wo      = (const float*)d_in[5];
    const float* norm1w  = (const float*)d_in[6];
    const float* norm2w  = (const float*)d_in[7];
    const float* wgate   = (const float*)d_in[8];
    const float* wup     = (const float*)d_in[9];
    const float* wdown   = (const float*)d_in[10];
    const int*   posids  = (const int*)d_in[11];
    float* out = (float*)d_out;

    float *q, *k, *v, *attn, *g, *u, *rope;
    __half *normed_h, *ctx_h, *normed2_h, *g_h;
    __half *wq_t, *wk_t, *wv_t, *wo_t, *wg_t, *wu_t, *wd_t;
    cudaGetSymbolAddress((void**)&q,         d_q);
    cudaGetSymbolAddress((void**)&k,         d_k);
    cudaGetSymbolAddress((void**)&v,         d_v);
    cudaGetSymbolAddress((void**)&attn,      d_attn);
    cudaGetSymbolAddress((void**)&g,         d_g);
    cudaGetSymbolAddress((void**)&u,         d_u);
    cudaGetSymbolAddress((void**)&rope,      d_rope);
    cudaGetSymbolAddress((void**)&normed_h,  d_normed_h);
    cudaGetSymbolAddress((void**)&ctx_h,     d_ctx_h);
    cudaGetSymbolAddress((void**)&normed2_h, d_normed2_h);
    cudaGetSymbolAddress((void**)&g_h,       d_g_h);
    cudaGetSymbolAddress((void**)&wq_t,      d_wq_t);
    cudaGetSymbolAddress((void**)&wk_t,      d_wk_t);
    cudaGetSymbolAddress((void**)&wv_t,      d_wv_t);
    cudaGetSymbolAddress((void**)&wo_t,      d_wo_t);
    cudaGetSymbolAddress((void**)&wg_t,      d_wg_t);
    cudaGetSymbolAddress((void**)&wu_t,      d_wu_t);
    cudaGetSymbolAddress((void**)&wd_t,      d_wd_t);

    cudaFuncSetAttribute(attn_mma, cudaFuncAttributeMaxDynamicSharedMemorySize, ATTM_SMEM);

    // 0) weight transpose + fp16 convert (pure function of inputs, every replay)
    transpose_half<<<dim3(2048/32, 2048/32), 256>>>(wq,    wq_t, 2048, 2048);
    transpose_half<<<dim3( 512/32, 2048/32), 256>>>(wk,    wk_t, 2048,  512);
    transpose_half<<<dim3( 512/32, 2048/32), 256>>>(wv,    wv_t, 2048,  512);
    transpose_half<<<dim3(2048/32, 2048/32), 256>>>(wo,    wo_t, 2048, 2048);
    transpose_half<<<dim3(8192/32, 2048/32), 256>>>(wgate, wg_t, 2048, 8192);
    transpose_half<<<dim3(8192/32, 2048/32), 256>>>(wup,   wu_t, 2048, 8192);
    transpose_half<<<dim3(2048/32, 8192/32), 256>>>(wdown, wd_t, 8192, 2048);

    // 1) pre-attention norm -> fp16
    rmsnorm_kernel<<<MROWS, 256>>>(hidden, nullptr, norm1w, normed_h);
    // 2) fused QKV (+ rope table)
    qkv_kernel<<<dim3(24, 16), 256>>>(normed_h, wq_t, wk_t, wv_t, q, k, v, posids, rope);
    // 3) RoPE apply (fp32)
    rope_apply<<<(MROWS * 40 * 32) / 256, 256>>>(q, k, rope);
    // 4) attention -> fp16 ctx
    attn_mma<<<dim3(8, 64), 256, ATTM_SMEM>>>(q, k, v, ctx_h);
    // 5) output projection
    gemm_h<<<dim3(16, 16), 256>>>(ctx_h, wo_t, attn, nullptr, HID, HID, 0);
    // 6) post-attention norm (fused residual) -> fp16
    rmsnorm_kernel<<<MROWS, 256>>>(attn, hidden, norm2w, normed2_h);
    // 7) FFN: up + gate one launch, then multiply -> fp16
    upgate_kernel<<<dim3(128, 16), 256>>>(normed2_h, wu_t, wg_t, u, g);
    swiglu_mul<<<(MROWS * FFND / 4 + 255) / 256, 256>>>(g, u, g_h, MROWS * FFND / 4);
    // 8) down projection + final residual
    gemm_h<<<dim3(16, 16), 256>>>(g_h, wd_t, out, attn, HID, FFND, 1);
}